// round 8
// baseline (speedup 1.0000x reference)
#include <cuda_runtime.h>
#include <cuda_bf16.h>
#include <math.h>

// Problem constants
#define BB 8
#define CC 128
#define HH 512
#define WW 512
#define HW (HH*WW)
#define KK 64
#define BK (BB*KK)      // 512 samples
#define NNEG 7
#define PP 4096
#define TAU 0.07f

// Sim tiling: block tile 64q x 128p, K=128. 4 warps, warp tile 32q x 64p.
#define TQS 64
#define TPS 128
#define NQT (BK/TQS)    // 8
#define NPT (PP/TPS)    // 32
#define GATHER_BLOCKS 32
#define SIM_BLOCKS (NQT*NPT)           // 256
#define GRID_MAIN (GATHER_BLOCKS + SIM_BLOCKS)  // 288 <= 296 (one wave @2/SM)

// Dynamic smem layout (bytes)
#define SM_Q 0                          // 64 rows x 512B (tf32, swizzled)
#define SM_P 32768                      // 128 rows x 512B
#define SM_PINV 98304                   // 128 floats
#define SM_RV 98816                     // 2 x 64 floats
#define SM_RI 99328                     // 2 x 64 ints
#define SMEM_TOTAL 99840

// k_loss structure
#define LB 64                           // loss blocks (8 samples each)
#define LGRP 8                          // 8 groups of 8 blocks

// Scratch (device globals; no allocation)
__device__ float g_qraw[BK*CC];
__device__ float g_qinv[BK];
__device__ float g_neglog[BK*NNEG];
__device__ float g_pmax[BK*NPT];
__device__ int   g_pidx[BK*NPT];
__device__ unsigned int g_qt_done[NQT];
__device__ double g_part[LB];
__device__ unsigned int g_lgrp[LGRP*32];   // 128B-padded group counters
__device__ unsigned int g_done2;

__device__ __forceinline__ float dot4(float4 a, float4 b) {
    return a.x*b.x + a.y*b.y + a.z*b.z + a.w*b.w;
}

__device__ __forceinline__ unsigned tf32c(float f) {
    unsigned r;
    asm("cvt.rna.tf32.f32 %0, %1;" : "=r"(r) : "f"(f));
    return r;
}

__device__ __forceinline__ unsigned smem_u32(const void* p) {
    unsigned r;
    asm("{ .reg .u64 t; cvta.to.shared.u64 t, %1; cvt.u32.u64 %0, t; }"
        : "=r"(r) : "l"(p));
    return r;
}

__device__ __forceinline__ void ldsm4(unsigned* d, unsigned addr) {
    asm volatile("ldmatrix.sync.aligned.m8n8.x4.shared.b16 {%0,%1,%2,%3}, [%4];"
        : "=r"(d[0]), "=r"(d[1]), "=r"(d[2]), "=r"(d[3]) : "r"(addr));
}
__device__ __forceinline__ void ldsm2(unsigned* d, unsigned addr) {
    asm volatile("ldmatrix.sync.aligned.m8n8.x2.shared.b16 {%0,%1}, [%2];"
        : "=r"(d[0]), "=r"(d[1]) : "r"(addr));
}
__device__ __forceinline__ void mma_tf32(float* c, const unsigned* a, const unsigned* b) {
    asm volatile(
        "mma.sync.aligned.m16n8k8.row.col.f32.tf32.tf32.f32 "
        "{%0,%1,%2,%3}, {%4,%5,%6,%7}, {%8,%9}, {%0,%1,%2,%3};"
        : "+f"(c[0]), "+f"(c[1]), "+f"(c[2]), "+f"(c[3])
        : "r"(a[0]), "r"(a[1]), "r"(a[2]), "r"(a[3]), "r"(b[0]), "r"(b[1]));
}

// ---------------------------------------------------------------------------
// K_MAIN: blocks 0..31 gather Q pixels, flag sim-ready EARLY, then compute
//         qinv + all 7 negative logits per sample (overlapped with sim).
//         blocks 32..287: load+cvt P tile, pool inv-norms, spin on gather
//         flag, then tf32 MMA + per-tile argmax.
// ---------------------------------------------------------------------------
__global__ void __launch_bounds__(128, 2) k_main(const float* __restrict__ qf,
                                                 const float* __restrict__ pool,
                                                 const int* __restrict__ qidx,
                                                 const float* __restrict__ negs) {
    extern __shared__ char sm[];
    const unsigned smb = smem_u32(sm);
    const int bid = blockIdx.x, tid = threadIdx.x;
    const int lane = tid & 31, wid = tid >> 5;

    if (bid < GATHER_BLOCKS) {
        // ---- Phase A: gather. block = 16 samples of qt = bid>>2; warp = 4.
        int qt = bid >> 2;
        int sBase = qt * 64 + (bid & 3) * 16;       // block's 16 samples
        int s0 = sBase + wid * 4;
        int idx[4];
#pragma unroll
        for (int i = 0; i < 4; i++) idx[i] = qidx[s0 + i];
        float v[4][4];
#pragma unroll
        for (int i = 0; i < 4; i++) {
            const float* base = qf + ((size_t)(qt * CC + lane * 4)) * HW + idx[i];
#pragma unroll
            for (int j = 0; j < 4; j++)
                v[i][j] = __ldcs(base + (size_t)j * HW);
        }
#pragma unroll
        for (int i = 0; i < 4; i++)
            *((float4*)(g_qraw + (size_t)(s0 + i) * CC + lane * 4)) =
                make_float4(v[i][0], v[i][1], v[i][2], v[i][3]);
        __threadfence();
        __syncthreads();
        if (tid == 0) atomicAdd(&g_qt_done[qt], 1u);   // unblock sim ASAP

        // ---- Phase B: per-sample inverse norms (from live registers).
#pragma unroll
        for (int i = 0; i < 4; i++) {
            float4 vi = make_float4(v[i][0], v[i][1], v[i][2], v[i][3]);
            float ss = dot4(vi, vi);
#pragma unroll
            for (int off = 16; off; off >>= 1)
                ss += __shfl_xor_sync(0xffffffffu, ss, off);
            if (lane == 0)
                g_qinv[s0 + i] = 1.0f / fmaxf(sqrtf(ss), 1e-12f);
        }
        __syncthreads();   // qinv + qraw visible block-wide

        // ---- Phase C: negative logits. 4-lane groups, 112 tasks (16s x 7n).
        int grp = tid >> 2, gl = tid & 3;
#pragma unroll
        for (int r = 0; r < 4; r++) {
            int t = grp + 32 * r;
            if (t < 112) {
                int si = t / NNEG, n = t - si * NNEG;
                int gq = sBase + si;
                const float4* qrow = (const float4*)(g_qraw + (size_t)gq * CC);
                const float4* nrow = (const float4*)(negs + ((size_t)gq * NNEG + n) * CC);
                float pd = 0.f, ns = 0.f;
#pragma unroll
                for (int k = 0; k < 8; k++) {
                    int c4 = gl + 4 * k;
                    float4 qv = qrow[c4];
                    float4 nv = nrow[c4];
                    pd += dot4(qv, nv);
                    ns += dot4(nv, nv);
                }
#pragma unroll
                for (int off = 1; off < 4; off <<= 1) {
                    pd += __shfl_xor_sync(0xffffffffu, pd, off);
                    ns += __shfl_xor_sync(0xffffffffu, ns, off);
                }
                if (gl == 0)
                    g_neglog[gq * NNEG + n] =
                        (pd * g_qinv[gq] / fmaxf(sqrtf(ns), 1e-12f)) / TAU;
            }
        }
        return;
    }

    // ---- sim block
    const int sb = bid - GATHER_BLOCKS;
    const int qt = sb >> 5, pt = sb & 31;
    const int qBase = qt * TQS, pBase = pt * TPS;

    // Phase 1: P tile global->smem, cvt to tf32, 32B-granule XOR swizzle.
    {
        const float4* psrc = (const float4*)(pool + (size_t)pBase * CC);
#pragma unroll
        for (int i = 0; i < 32; i++) {
            int e = tid + i * 128;           // 0..4095
            int r = e >> 5, kq = e & 31;
            float4 w = psrc[e];
            uint4 t = make_uint4(tf32c(w.x), tf32c(w.y), tf32c(w.z), tf32c(w.w));
            unsigned off = SM_P + r * 512 + ((((kq >> 1) ^ (r & 7))) << 5) + ((kq & 1) << 4);
            *((uint4*)(sm + off)) = t;
        }
    }
    __syncthreads();

    // Phase 2: pool inverse norms from smem.
    {
        int r = tid;
        float ss = 0.f;
#pragma unroll
        for (int kq = 0; kq < 32; kq++) {
            unsigned off = SM_P + r * 512 + ((((kq >> 1) ^ (r & 7))) << 5) + ((kq & 1) << 4);
            float4 w = *((const float4*)(sm + off));
            ss += dot4(w, w);
        }
        ((float*)(sm + SM_PINV))[r] = rsqrtf(fmaxf(ss, 1e-24f));
    }

    // Phase 3: wait for this qt's gather (4 producer blocks).
    if (tid == 0) {
        while (((volatile unsigned*)g_qt_done)[qt] < 4u) __nanosleep(64);
    }
    __syncthreads();
    __threadfence();

    // Phase 4: Q tile g_qraw->smem, cvt tf32, same swizzle.
    {
        const float4* qsrc = (const float4*)(g_qraw + (size_t)qBase * CC);
#pragma unroll
        for (int i = 0; i < 16; i++) {
            int e = tid + i * 128;           // 0..2047
            int r = e >> 5, kq = e & 31;
            float4 w = qsrc[e];
            uint4 t = make_uint4(tf32c(w.x), tf32c(w.y), tf32c(w.z), tf32c(w.w));
            unsigned off = SM_Q + r * 512 + ((((kq >> 1) ^ (r & 7))) << 5) + ((kq & 1) << 4);
            *((uint4*)(sm + off)) = t;
        }
    }
    __syncthreads();

    // Phase 5: mainloop. warp (qw, pw): 32q x 64p; m16n8k8 tf32.
    const int qw = wid & 1, pw = wid >> 1;
    const int x7 = lane & 7;
    unsigned Abase = smb + SM_Q + (unsigned)((qw * 32 + (lane & 15)) * 512) + ((lane >> 4) << 4);
    unsigned Amb1 = Abase + 16 * 512;
    unsigned Bbase[8];
#pragma unroll
    for (int nb = 0; nb < 8; nb++)
        Bbase[nb] = smb + SM_P + (unsigned)((pw * 64 + nb * 8 + (lane & 7)) * 512) + (((lane >> 3) & 1) << 4);

    float acc[2][8][4];
#pragma unroll
    for (int mb = 0; mb < 2; mb++)
#pragma unroll
        for (int nb = 0; nb < 8; nb++)
#pragma unroll
            for (int c = 0; c < 4; c++) acc[mb][nb][c] = 0.f;

#pragma unroll
    for (int ks = 0; ks < 16; ks++) {
        unsigned koff = (unsigned)((ks ^ x7) << 5);
        unsigned a0[4], a1[4];
        ldsm4(a0, Abase + koff);
        ldsm4(a1, Amb1 + koff);
#pragma unroll
        for (int nb = 0; nb < 8; nb++) {
            unsigned bb[2];
            ldsm2(bb, Bbase[nb] + koff);
            mma_tf32(acc[0][nb], a0, bb);
            mma_tf32(acc[1][nb], a1, bb);
        }
    }

    // Phase 6: epilogue — scale by pinv, per-q argmax over this 128-p tile.
    const float* s_pinv = (const float*)(sm + SM_PINV);
    float* s_rv = (float*)(sm + SM_RV);
    int*   s_ri = (int*)(sm + SM_RI);
#pragma unroll
    for (int mb = 0; mb < 2; mb++) {
#pragma unroll
        for (int half = 0; half < 2; half++) {
            int q_blk = qw * 32 + mb * 16 + (lane >> 2) + half * 8;
            float best = -1e30f; int bi = 0;
#pragma unroll
            for (int nb = 0; nb < 8; nb++) {
#pragma unroll
                for (int c2 = 0; c2 < 2; c2++) {
                    int pl = pw * 64 + nb * 8 + (lane & 3) * 2 + c2;
                    float v = acc[mb][nb][half * 2 + c2] * s_pinv[pl];
                    int pg = pBase + pl;
                    if (v > best) { best = v; bi = pg; }
                }
            }
#pragma unroll
            for (int off = 1; off < 4; off <<= 1) {
                float ov = __shfl_xor_sync(0xffffffffu, best, off);
                int   oi = __shfl_xor_sync(0xffffffffu, bi, off);
                if (ov > best || (ov == best && oi < bi)) { best = ov; bi = oi; }
            }
            if ((lane & 3) == 0) {
                s_rv[pw * 64 + q_blk] = best;
                s_ri[pw * 64 + q_blk] = bi;
            }
        }
    }
    __syncthreads();
    if (tid < 64) {
        float v0 = s_rv[tid], v1 = s_rv[64 + tid];
        int   i0 = s_ri[tid], i1 = s_ri[64 + tid];
        float bv; int bi;
        if (v1 > v0 || (v1 == v0 && i1 < i0)) { bv = v1; bi = i1; }
        else                                   { bv = v0; bi = i0; }
        int gq = qBase + tid;
        g_pmax[gq * NPT + pt] = bv;
        g_pidx[gq * NPT + pt] = bi;
    }
}

// ---------------------------------------------------------------------------
// K_LOSS: 64 blocks x 256 threads, warp per sample (8 samples/block).
// Per sample: merge argmaxes, fp32 positive logit, softmax with precomputed
// negative logits. Hierarchical low-contention convergence, deterministic
// ordered final sum. Resets all cross-launch scratch.
// ---------------------------------------------------------------------------
__global__ void k_loss(const float* __restrict__ pool,
                       float* __restrict__ out) {
    int w = threadIdx.x >> 5, lane = threadIdx.x & 31;
    int gq = blockIdx.x * 8 + w;
    __shared__ float s_loss[8];

    // merge 32 per-tile argmaxes (tie -> smallest p = first occurrence)
    float v = g_pmax[gq * NPT + lane];
    int idx = g_pidx[gq * NPT + lane];
#pragma unroll
    for (int off = 16; off; off >>= 1) {
        float ov = __shfl_xor_sync(0xffffffffu, v, off);
        int   oi = __shfl_xor_sync(0xffffffffu, idx, off);
        if (ov > v || (ov == v && oi < idx)) { v = ov; idx = oi; }
    }
    int pstar = idx;

    float4 q  = ((const float4*)(g_qraw + (size_t)gq * CC))[lane];
    float4 pp = ((const float4*)(pool + (size_t)pstar * CC))[lane];
    float d  = dot4(q, pp);
    float ps = dot4(pp, pp);
#pragma unroll
    for (int off = 16; off; off >>= 1) {
        d  += __shfl_xor_sync(0xffffffffu, d, off);
        ps += __shfl_xor_sync(0xffffffffu, ps, off);
    }

    if (lane == 0) {
        float pinv = 1.0f / fmaxf(sqrtf(ps), 1e-12f);
        float l0 = (d * g_qinv[gq] * pinv) / TAU;
        float ln[NNEG];
#pragma unroll
        for (int n = 0; n < NNEG; n++) ln[n] = g_neglog[gq * NNEG + n];
        float m = l0;
#pragma unroll
        for (int n = 0; n < NNEG; n++) m = fmaxf(m, ln[n]);
        float se = expf(l0 - m);
#pragma unroll
        for (int n = 0; n < NNEG; n++) se += expf(ln[n] - m);
        s_loss[w] = logf(se) - (l0 - m);
    }
    __syncthreads();

    if (threadIdx.x == 0) {
        double part = 0.0;
#pragma unroll
        for (int i = 0; i < 8; i++) part += (double)s_loss[i];
        g_part[blockIdx.x] = part;
        __threadfence();

        int grp = blockIdx.x >> 3;
        unsigned r = atomicAdd(&g_lgrp[grp * 32], 1u);
        if (r == 7u) {                       // last block of this 8-group
            unsigned r2 = atomicAdd(&g_done2, 1u);
            if (r2 == (unsigned)(LGRP - 1)) {   // last group overall
                __threadfence();
                double s = 0.0;
#pragma unroll
                for (int i = 0; i < LB; i++)
                    s += ((volatile double*)g_part)[i];
                out[0] = (float)(s / (double)BK);
                // reset cross-launch scratch for next graph replay
                g_done2 = 0u;
#pragma unroll
                for (int i = 0; i < LGRP; i++) g_lgrp[i * 32] = 0u;
#pragma unroll
                for (int i = 0; i < NQT; i++) g_qt_done[i] = 0u;
            }
        }
    }
}

// ---------------------------------------------------------------------------
extern "C" void kernel_launch(void* const* d_in, const int* in_sizes, int n_in,
                              void* d_out, int out_size) {
    const float* qf   = (const float*)d_in[0];   // [B,C,H,W]
    const float* pool = (const float*)d_in[1];   // [P,C]
    const float* negs = (const float*)d_in[2];   // [B,K,N,C]
    const int*   qidx = (const int*)d_in[3];     // [B,K]
    float* out = (float*)d_out;

    cudaFuncSetAttribute(k_main,
                         cudaFuncAttributeMaxDynamicSharedMemorySize, SMEM_TOTAL);

    k_main<<<GRID_MAIN, 128, SMEM_TOTAL>>>(qf, pool, qidx, negs);
    k_loss<<<LB, 256>>>(pool, out);
}

// round 9
// speedup vs baseline: 1.1271x; 1.1271x over previous
#include <cuda_runtime.h>
#include <cuda_bf16.h>
#include <math.h>

// Problem constants
#define BB 8
#define CC 128
#define HH 512
#define WW 512
#define HW (HH*WW)
#define KK 64
#define BK (BB*KK)      // 512 samples
#define NNEG 7
#define PP 4096
#define TAU 0.07f

// Sim tiling: block tile 64q x 128p, K=128. 4 warps, warp tile 32q x 64p.
#define TQS 64
#define TPS 128
#define NQT (BK/TQS)    // 8
#define NPT (PP/TPS)    // 32
#define GATHER_BLOCKS 32
#define SIM_BLOCKS (NQT*NPT)           // 256
#define GRID_MAIN (GATHER_BLOCKS + SIM_BLOCKS)  // 288 <= 296 (one wave @2/SM)

// Dynamic smem layout (bytes)
#define SM_Q 0                          // 64 rows x 512B (tf32, swizzled)
#define SM_P 32768                      // 128 rows x 512B
#define SM_PINV 98304                   // 128 floats
#define SMEM_TOTAL 98816

// Scratch (device globals; no allocation)
__device__ float g_qraw[BK*CC];
__device__ float g_qinv[BK];
__device__ float g_neglog[BK*NNEG];
__device__ unsigned long long g_best[BK];   // packed (mono(sim)<<32)|(~p)
__device__ float g_loss[BK];
__device__ unsigned int g_qt_done[NQT];
__device__ unsigned int g_done2;

__device__ __forceinline__ float dot4(float4 a, float4 b) {
    return a.x*b.x + a.y*b.y + a.z*b.z + a.w*b.w;
}

// monotone-ordered packing of (sim value, pool index); u64 max == argmax with
// smallest-index tie-break (first occurrence), order-independent.
__device__ __forceinline__ unsigned long long packmax(float v, int pg) {
    unsigned b = __float_as_uint(v);
    unsigned mono = (b & 0x80000000u) ? ~b : (b | 0x80000000u);
    return ((unsigned long long)mono << 32) | (unsigned)(0xFFFFFFFFu - pg);
}

__device__ __forceinline__ unsigned tf32c(float f) {
    unsigned r;
    asm("cvt.rna.tf32.f32 %0, %1;" : "=r"(r) : "f"(f));
    return r;
}

__device__ __forceinline__ unsigned smem_u32(const void* p) {
    unsigned r;
    asm("{ .reg .u64 t; cvta.to.shared.u64 t, %1; cvt.u32.u64 %0, t; }"
        : "=r"(r) : "l"(p));
    return r;
}

__device__ __forceinline__ void ldsm4(unsigned* d, unsigned addr) {
    asm volatile("ldmatrix.sync.aligned.m8n8.x4.shared.b16 {%0,%1,%2,%3}, [%4];"
        : "=r"(d[0]), "=r"(d[1]), "=r"(d[2]), "=r"(d[3]) : "r"(addr));
}
__device__ __forceinline__ void ldsm2(unsigned* d, unsigned addr) {
    asm volatile("ldmatrix.sync.aligned.m8n8.x2.shared.b16 {%0,%1}, [%2];"
        : "=r"(d[0]), "=r"(d[1]) : "r"(addr));
}
__device__ __forceinline__ void mma_tf32(float* c, const unsigned* a, const unsigned* b) {
    asm volatile(
        "mma.sync.aligned.m16n8k8.row.col.f32.tf32.tf32.f32 "
        "{%0,%1,%2,%3}, {%4,%5,%6,%7}, {%8,%9}, {%0,%1,%2,%3};"
        : "+f"(c[0]), "+f"(c[1]), "+f"(c[2]), "+f"(c[3])
        : "r"(a[0]), "r"(a[1]), "r"(a[2]), "r"(a[3]), "r"(b[0]), "r"(b[1]));
}

// ---------------------------------------------------------------------------
// K_MAIN: blocks 0..31 gather Q pixels, flag sim-ready EARLY, then compute
//         qinv + all 7 negative logits (overlapped with sim blocks).
//         blocks 32..287: P tile + pool inv-norms, spin on gather flag,
//         tf32 MMA, epilogue atomicMax-packed argmax straight to g_best.
// ---------------------------------------------------------------------------
__global__ void __launch_bounds__(128, 2) k_main(const float* __restrict__ qf,
                                                 const float* __restrict__ pool,
                                                 const int* __restrict__ qidx,
                                                 const float* __restrict__ negs) {
    extern __shared__ char sm[];
    const unsigned smb = smem_u32(sm);
    const int bid = blockIdx.x, tid = threadIdx.x;
    const int lane = tid & 31, wid = tid >> 5;

    if (bid < GATHER_BLOCKS) {
        // ---- Phase A: gather. block = 16 samples of qt = bid>>2; warp = 4.
        int qt = bid >> 2;
        int sBase = qt * 64 + (bid & 3) * 16;
        int s0 = sBase + wid * 4;
        int idx[4];
#pragma unroll
        for (int i = 0; i < 4; i++) idx[i] = qidx[s0 + i];
        float v[4][4];
#pragma unroll
        for (int i = 0; i < 4; i++) {
            const float* base = qf + ((size_t)(qt * CC + lane * 4)) * HW + idx[i];
#pragma unroll
            for (int j = 0; j < 4; j++)
                v[i][j] = __ldcs(base + (size_t)j * HW);
        }
#pragma unroll
        for (int i = 0; i < 4; i++)
            *((float4*)(g_qraw + (size_t)(s0 + i) * CC + lane * 4)) =
                make_float4(v[i][0], v[i][1], v[i][2], v[i][3]);
        __threadfence();
        __syncthreads();
        if (tid == 0) atomicAdd(&g_qt_done[qt], 1u);   // unblock sim ASAP

        // ---- Phase B: per-sample inverse norms (from live registers).
#pragma unroll
        for (int i = 0; i < 4; i++) {
            float4 vi = make_float4(v[i][0], v[i][1], v[i][2], v[i][3]);
            float ss = dot4(vi, vi);
#pragma unroll
            for (int off = 16; off; off >>= 1)
                ss += __shfl_xor_sync(0xffffffffu, ss, off);
            if (lane == 0)
                g_qinv[s0 + i] = 1.0f / fmaxf(sqrtf(ss), 1e-12f);
        }
        __syncthreads();

        // ---- Phase C: negative logits. 4-lane groups, 112 tasks (16s x 7n).
        int grp = tid >> 2, gl = tid & 3;
#pragma unroll
        for (int r = 0; r < 4; r++) {
            int t = grp + 32 * r;
            if (t < 112) {
                int si = t / NNEG, n = t - si * NNEG;
                int gq = sBase + si;
                const float4* qrow = (const float4*)(g_qraw + (size_t)gq * CC);
                const float4* nrow = (const float4*)(negs + ((size_t)gq * NNEG + n) * CC);
                float pd = 0.f, ns = 0.f;
#pragma unroll
                for (int k = 0; k < 8; k++) {
                    int c4 = gl + 4 * k;
                    float4 qv = qrow[c4];
                    float4 nv = nrow[c4];
                    pd += dot4(qv, nv);
                    ns += dot4(nv, nv);
                }
#pragma unroll
                for (int off = 1; off < 4; off <<= 1) {
                    pd += __shfl_xor_sync(0xffffffffu, pd, off);
                    ns += __shfl_xor_sync(0xffffffffu, ns, off);
                }
                if (gl == 0)
                    g_neglog[gq * NNEG + n] =
                        (pd * g_qinv[gq] / fmaxf(sqrtf(ns), 1e-12f)) / TAU;
            }
        }
        return;
    }

    // ---- sim block
    const int sb = bid - GATHER_BLOCKS;
    const int qt = sb >> 5, pt = sb & 31;
    const int qBase = qt * TQS, pBase = pt * TPS;

    // Phase 1: P tile global->smem, cvt to tf32, 32B-granule XOR swizzle.
    {
        const float4* psrc = (const float4*)(pool + (size_t)pBase * CC);
#pragma unroll
        for (int i = 0; i < 32; i++) {
            int e = tid + i * 128;           // 0..4095
            int r = e >> 5, kq = e & 31;
            float4 w = psrc[e];
            uint4 t = make_uint4(tf32c(w.x), tf32c(w.y), tf32c(w.z), tf32c(w.w));
            unsigned off = SM_P + r * 512 + ((((kq >> 1) ^ (r & 7))) << 5) + ((kq & 1) << 4);
            *((uint4*)(sm + off)) = t;
        }
    }
    __syncthreads();

    // Phase 2: pool inverse norms from smem.
    {
        int r = tid;
        float ss = 0.f;
#pragma unroll
        for (int kq = 0; kq < 32; kq++) {
            unsigned off = SM_P + r * 512 + ((((kq >> 1) ^ (r & 7))) << 5) + ((kq & 1) << 4);
            float4 w = *((const float4*)(sm + off));
            ss += dot4(w, w);
        }
        ((float*)(sm + SM_PINV))[r] = rsqrtf(fmaxf(ss, 1e-24f));
    }

    // Phase 3: wait for this qt's gather (4 producer blocks).
    if (tid == 0) {
        while (((volatile unsigned*)g_qt_done)[qt] < 4u) __nanosleep(64);
    }
    __syncthreads();
    __threadfence();

    // Phase 4: Q tile g_qraw->smem, cvt tf32, same swizzle.
    {
        const float4* qsrc = (const float4*)(g_qraw + (size_t)qBase * CC);
#pragma unroll
        for (int i = 0; i < 16; i++) {
            int e = tid + i * 128;           // 0..2047
            int r = e >> 5, kq = e & 31;
            float4 w = qsrc[e];
            uint4 t = make_uint4(tf32c(w.x), tf32c(w.y), tf32c(w.z), tf32c(w.w));
            unsigned off = SM_Q + r * 512 + ((((kq >> 1) ^ (r & 7))) << 5) + ((kq & 1) << 4);
            *((uint4*)(sm + off)) = t;
        }
    }
    __syncthreads();

    // Phase 5: mainloop. warp (qw, pw): 32q x 64p; m16n8k8 tf32.
    const int qw = wid & 1, pw = wid >> 1;
    const int x7 = lane & 7;
    unsigned Abase = smb + SM_Q + (unsigned)((qw * 32 + (lane & 15)) * 512) + ((lane >> 4) << 4);
    unsigned Amb1 = Abase + 16 * 512;
    unsigned Bbase[8];
#pragma unroll
    for (int nb = 0; nb < 8; nb++)
        Bbase[nb] = smb + SM_P + (unsigned)((pw * 64 + nb * 8 + (lane & 7)) * 512) + (((lane >> 3) & 1) << 4);

    float acc[2][8][4];
#pragma unroll
    for (int mb = 0; mb < 2; mb++)
#pragma unroll
        for (int nb = 0; nb < 8; nb++)
#pragma unroll
            for (int c = 0; c < 4; c++) acc[mb][nb][c] = 0.f;

#pragma unroll
    for (int ks = 0; ks < 16; ks++) {
        unsigned koff = (unsigned)((ks ^ x7) << 5);
        unsigned a0[4], a1[4];
        ldsm4(a0, Abase + koff);
        ldsm4(a1, Amb1 + koff);
#pragma unroll
        for (int nb = 0; nb < 8; nb++) {
            unsigned bb[2];
            ldsm2(bb, Bbase[nb] + koff);
            mma_tf32(acc[0][nb], a0, bb);
            mma_tf32(acc[1][nb], a1, bb);
        }
    }

    // Phase 6: epilogue — scale by pinv, pack, 4-lane merge, atomicMax to
    // the per-sample slot. No smem merge, no per-tile arrays.
    const float* s_pinv = (const float*)(sm + SM_PINV);
#pragma unroll
    for (int mb = 0; mb < 2; mb++) {
#pragma unroll
        for (int half = 0; half < 2; half++) {
            int q_blk = qw * 32 + mb * 16 + (lane >> 2) + half * 8;
            unsigned long long best = 0ULL;
#pragma unroll
            for (int nb = 0; nb < 8; nb++) {
#pragma unroll
                for (int c2 = 0; c2 < 2; c2++) {
                    int pl = pw * 64 + nb * 8 + (lane & 3) * 2 + c2;
                    float v = acc[mb][nb][half * 2 + c2] * s_pinv[pl];
                    unsigned long long pk = packmax(v, pBase + pl);
                    if (pk > best) best = pk;
                }
            }
#pragma unroll
            for (int off = 1; off < 4; off <<= 1) {
                unsigned long long ob = __shfl_xor_sync(0xffffffffu, best, off);
                if (ob > best) best = ob;
            }
            if ((lane & 3) == 0)
                atomicMax(&g_best[qBase + q_blk], best);
        }
    }
}

// ---------------------------------------------------------------------------
// K_LOSS: 128 blocks x 128 threads, warp = one sample.
// Read packed argmax, fp32 positive logit, softmax with precomputed neg
// logits. Last block: deterministic fixed-order tree sum -> mean.
// Resets all cross-launch scratch (g_best per warp, counters by reducer).
// ---------------------------------------------------------------------------
__global__ void k_loss(const float* __restrict__ pool,
                       float* __restrict__ out) {
    int w = threadIdx.x >> 5, lane = threadIdx.x & 31;
    int gq = blockIdx.x * 4 + w;
    int tid = threadIdx.x;

    unsigned long long pk = 0ULL;
    if (lane == 0) { pk = g_best[gq]; g_best[gq] = 0ULL; }
    pk = __shfl_sync(0xffffffffu, pk, 0);
    int pstar = (int)(0xFFFFFFFFu - (unsigned)(pk & 0xFFFFFFFFu));

    float4 q  = ((const float4*)(g_qraw + (size_t)gq * CC))[lane];
    float4 pp = ((const float4*)(pool + (size_t)pstar * CC))[lane];
    float d  = dot4(q, pp);
    float ps = dot4(pp, pp);
#pragma unroll
    for (int off = 16; off; off >>= 1) {
        d  += __shfl_xor_sync(0xffffffffu, d, off);
        ps += __shfl_xor_sync(0xffffffffu, ps, off);
    }

    if (lane == 0) {
        float pinv = 1.0f / fmaxf(sqrtf(ps), 1e-12f);
        float l0 = (d * g_qinv[gq] * pinv) / TAU;
        float ln[NNEG];
#pragma unroll
        for (int n = 0; n < NNEG; n++) ln[n] = g_neglog[gq * NNEG + n];
        float m = l0;
#pragma unroll
        for (int n = 0; n < NNEG; n++) m = fmaxf(m, ln[n]);
        float se = expf(l0 - m);
#pragma unroll
        for (int n = 0; n < NNEG; n++) se += expf(ln[n] - m);
        g_loss[gq] = logf(se) - (l0 - m);
    }
    __syncthreads();

    __shared__ int s_last;
    if (tid == 0) {
        __threadfence();
        s_last = (atomicAdd(&g_done2, 1u) == (unsigned)(gridDim.x - 1));
    }
    __syncthreads();

    if (s_last && w == 0) {
        __threadfence();
        // deterministic: fixed lane->range partials, fixed shfl tree.
        double s = 0.0;
#pragma unroll
        for (int i = 0; i < 16; i++)
            s += (double)((volatile float*)g_loss)[lane * 16 + i];
#pragma unroll
        for (int off = 16; off; off >>= 1)
            s += __shfl_xor_sync(0xffffffffu, s, off);
        if (lane == 0) {
            out[0] = (float)(s / (double)BK);
            g_done2 = 0u;
#pragma unroll
            for (int i = 0; i < NQT; i++) g_qt_done[i] = 0u;
        }
    }
}

// ---------------------------------------------------------------------------
extern "C" void kernel_launch(void* const* d_in, const int* in_sizes, int n_in,
                              void* d_out, int out_size) {
    const float* qf   = (const float*)d_in[0];   // [B,C,H,W]
    const float* pool = (const float*)d_in[1];   // [P,C]
    const float* negs = (const float*)d_in[2];   // [B,K,N,C]
    const int*   qidx = (const int*)d_in[3];     // [B,K]
    float* out = (float*)d_out;

    cudaFuncSetAttribute(k_main,
                         cudaFuncAttributeMaxDynamicSharedMemorySize, SMEM_TOTAL);

    k_main<<<GRID_MAIN, 128, SMEM_TOTAL>>>(qf, pool, qidx, negs);
    k_loss<<<128, 128>>>(pool, out);
}